// round 2
// baseline (speedup 1.0000x reference)
#include <cuda_runtime.h>

// Ordered_GCN: B=64, N=207, K=32, C=8, D_IN=64, D_OUT=64
// tokens = B*N = 13248. Per token:
//   mean[c][d] = (1/max(cnt_c,1)) * sum_{k: idx[k]==c} win[k][d]
//   out[c][o]  = tanh( sum_d mean[c][d] * W[c][o][d] )
//
// Persistent kernel: 1 CTA/SM, 512 threads. Thread tid owns output (c,o):
// c = tid>>6, o = tid&63. W[c][o][:] lives in registers as 32 packed f32x2.
// Input tile (8KB) double-buffered via cp.async.

#define KNB   32
#define DIN   64
#define DOUT  64
#define NCLS  8
#define NTHR  512
#define TOKEN_OUT (NCLS * DOUT)      // 512
#define TOKEN_IN  (KNB * DIN)        // 2048 floats

__device__ __forceinline__ unsigned long long ffma2(unsigned long long a,
                                                    unsigned long long b,
                                                    unsigned long long c) {
    unsigned long long d;
    asm("fma.rn.f32x2 %0, %1, %2, %3;" : "=l"(d) : "l"(a), "l"(b), "l"(c));
    return d;
}

__device__ __forceinline__ unsigned long long pack_f2(float x, float y) {
    unsigned long long r;
    asm("mov.b64 %0, {%1, %2};" : "=l"(r) : "f"(x), "f"(y));
    return r;
}

__device__ __forceinline__ void unpack_f2(unsigned long long v, float& x, float& y) {
    asm("mov.b64 {%0, %1}, %2;" : "=f"(x), "=f"(y) : "l"(v));
}

__device__ __forceinline__ void cp_async16(void* smem, const void* gmem) {
    unsigned saddr = (unsigned)__cvta_generic_to_shared(smem);
    asm volatile("cp.async.cg.shared.global [%0], [%1], 16;" :: "r"(saddr), "l"(gmem));
}

__global__ void __launch_bounds__(NTHR, 1)
ordered_gcn_kernel(const int* __restrict__ idx,
                   const float* __restrict__ win,
                   const float* __restrict__ W,
                   float* __restrict__ out,
                   int total)
{
    __shared__ float win_sh[2][TOKEN_IN];   // 2 x 8KB
    __shared__ int   idx_sh[2][KNB];        // 2 x 128B
    __shared__ float mean_sh[NCLS * DIN];   // 2KB

    const int tid  = threadIdx.x;
    const int lane = tid & 31;
    const int c    = tid >> 6;   // class owned by this thread (uniform per warp)
    const int o    = tid & 63;   // output (and scatter d) index

    // ---- Load W[c][o][0:64] into registers as 32 packed f32x2 ----
    unsigned long long w[32];
    {
        const float4* gw = reinterpret_cast<const float4*>(W + ((c * DOUT + o) * DIN));
        #pragma unroll
        for (int j = 0; j < 16; j++) {
            float4 v = gw[j];
            w[2 * j]     = pack_f2(v.x, v.y);
            w[2 * j + 1] = pack_f2(v.z, v.w);
        }
    }

    const int stride = gridDim.x;
    const int t0 = blockIdx.x;

    // ---- Prefetch tokens t0 and t0+stride into buffers 0 and 1 ----
    {
        int t = t0;
        if (t < total) {
            cp_async16(&win_sh[0][tid * 4], win + (size_t)t * TOKEN_IN + tid * 4);
            if (tid < 8) cp_async16(&idx_sh[0][tid * 4], idx + (size_t)t * KNB + tid * 4);
        }
        asm volatile("cp.async.commit_group;");
        t = t0 + stride;
        if (t < total) {
            cp_async16(&win_sh[1][tid * 4], win + (size_t)t * TOKEN_IN + tid * 4);
            if (tid < 8) cp_async16(&idx_sh[1][tid * 4], idx + (size_t)t * KNB + tid * 4);
        }
        asm volatile("cp.async.commit_group;");
    }

    int buf = 0;
    for (int t = t0; t < total; t += stride) {
        // Wait until current buffer's copy is complete (allow 1 group in flight)
        asm volatile("cp.async.wait_group 1;");
        __syncthreads();

        // ---- Class membership mask (per-warp ballot; c is warp-uniform) ----
        const int my = idx_sh[buf][lane];
        unsigned mask = __ballot_sync(0xffffffffu, my == c);
        const int cnt = __popc(mask);
        const float rc = 1.0f / (float)(cnt > 0 ? cnt : 1);

        // ---- Scatter-mean: sum over members of class c, column o ----
        float s = 0.0f;
        unsigned m = mask;
        while (m) {
            int k = __ffs(m) - 1;
            m &= m - 1;
            s += win_sh[buf][k * DIN + o];
        }
        mean_sh[c * DIN + o] = s * rc;
        __syncthreads();

        // ---- Prefetch token t + 2*stride into the buffer we just consumed ----
        {
            int tp = t + 2 * stride;
            if (tp < total) {
                cp_async16(&win_sh[buf][tid * 4], win + (size_t)tp * TOKEN_IN + tid * 4);
                if (tid < 8) cp_async16(&idx_sh[buf][tid * 4], idx + (size_t)tp * KNB + tid * 4);
            }
            asm volatile("cp.async.commit_group;");
        }

        // ---- GEMV: out[c][o] = tanh( dot(mean[c][:], W[c][o][:]) ) ----
        const unsigned long long* m2 =
            reinterpret_cast<const unsigned long long*>(mean_sh + c * DIN);
        unsigned long long acc0 = 0ULL;  // bits of (0.0f, 0.0f)
        unsigned long long acc1 = 0ULL;
        #pragma unroll
        for (int j = 0; j < 32; j += 2) {
            acc0 = ffma2(m2[j],     w[j],     acc0);
            acc1 = ffma2(m2[j + 1], w[j + 1], acc1);
        }
        float x0, y0, x1, y1;
        unpack_f2(acc0, x0, y0);
        unpack_f2(acc1, x1, y1);
        out[(size_t)t * TOKEN_OUT + tid] = tanhf((x0 + x1) + (y0 + y1));

        buf ^= 1;
    }
}

extern "C" void kernel_launch(void* const* d_in, const int* in_sizes, int n_in,
                              void* d_out, int out_size) {
    const int*   idx = (const int*)d_in[0];     // [B,N,K] int32
    const float* win = (const float*)d_in[1];   // [B,N,K,D_IN] f32
    const float* W   = (const float*)d_in[2];   // [C,D_OUT,D_IN] f32
    float* out = (float*)d_out;                 // [B,N,C,D_OUT] f32

    const int total = in_sizes[0] / KNB;        // B*N tokens

    int sms = 148;
    int dev = 0;
    cudaGetDevice(&dev);
    cudaDeviceGetAttribute(&sms, cudaDevAttrMultiProcessorCount, dev);
    int grid = (sms < total) ? sms : total;

    ordered_gcn_kernel<<<grid, NTHR>>>(idx, win, W, out, total);
}

// round 3
// speedup vs baseline: 1.3398x; 1.3398x over previous
#include <cuda_runtime.h>

// Ordered_GCN: B=64, N=207, K=32, C=8, D_IN=64, D_OUT=64, tokens = 13248.
// Per token: class-masked mean over 32 neighbors, per-class 64x64 GEMV, tanh.
//
// R3 design: persistent CTA (1/SM, 512 thr). Warp w owns (class c=w>>1,
// outputs o = (w&1)*32 + lane). Per-token processing is WARP-LOCAL:
//  - ballot on idx -> member mask, popcount
//  - lane accumulates class-sum pair (d=2*lane, 2*lane+1) from smem tile
//  - stage pair in warp-private smem slot, broadcast-read for GEMV
//  - 32x fma.rn.f32x2 against register-resident W row, fast tanh, store.
// Block barriers only for buffer lifetime: CHUNK=8 tokens per buffer,
// double buffered via cp.async -> 2 __syncthreads per 8 tokens.

#define KNB   32
#define DIN   64
#define NCLS  8
#define NTHR  512
#define CHUNK 8
#define TOKEN_IN  2048   // floats per token (32*64)
#define TOKEN_OUT 512    // floats per token (8*64)

#define WIN_FLOATS (2 * CHUNK * TOKEN_IN)   // 32768 floats = 128KB
#define IDX_INTS   (2 * CHUNK * KNB)        // 512 ints = 2KB
#define SMEM_BYTES (WIN_FLOATS * 4 + IDX_INTS * 4 + 16 * 32 * 8)  // +4KB mean staging

typedef unsigned long long u64;

__device__ __forceinline__ u64 ffma2(u64 a, u64 b, u64 c) {
    u64 d;
    asm("fma.rn.f32x2 %0, %1, %2, %3;" : "=l"(d) : "l"(a), "l"(b), "l"(c));
    return d;
}
__device__ __forceinline__ u64 pack_f2(float x, float y) {
    u64 r; asm("mov.b64 %0, {%1, %2};" : "=l"(r) : "f"(x), "f"(y)); return r;
}
__device__ __forceinline__ void unpack_f2(u64 v, float& x, float& y) {
    asm("mov.b64 {%0, %1}, %2;" : "=f"(x), "=f"(y) : "l"(v));
}
__device__ __forceinline__ void cp_async16(void* smem, const void* gmem) {
    unsigned saddr = (unsigned)__cvta_generic_to_shared(smem);
    asm volatile("cp.async.cg.shared.global [%0], [%1], 16;" :: "r"(saddr), "l"(gmem));
}

__global__ void __launch_bounds__(NTHR, 1)
ordered_gcn_kernel(const int* __restrict__ idx,
                   const float* __restrict__ win,
                   const float* __restrict__ W,
                   float* __restrict__ out,
                   int total, int ngroups)
{
    extern __shared__ float smem[];
    float* win_s  = smem;                                   // [2][CHUNK][2048]
    int*   idx_s  = (int*)(smem + WIN_FLOATS);              // [2][CHUNK][32]
    u64*   mean2  = (u64*)(idx_s + IDX_INTS);               // [16][32] f32x2

    const int tid  = threadIdx.x;
    const int lane = tid & 31;
    const int warp = tid >> 5;
    const int c    = warp >> 1;            // class (uniform per warp)
    const int o    = ((warp & 1) << 5) | lane;   // output column 0..63

    // ---- W[c][o][0:64] register-resident as 32 packed f32x2 ----
    u64 w[32];
    {
        const float4* gw = (const float4*)(W + ((c * DIN + o) * DIN));
        #pragma unroll
        for (int j = 0; j < 16; j++) {
            float4 v = gw[j];
            w[2*j]   = pack_f2(v.x, v.y);
            w[2*j+1] = pack_f2(v.z, v.w);
        }
    }

    const int grid = gridDim.x;
    const int bid  = blockIdx.x;

    // ---- prefetch helper (issues one chunk's copies into buffer b) ----
    auto issue_group = [&](int g, int b) {
        if (g < ngroups) {
            int base = g * CHUNK;
            float* wdst = win_s + b * (CHUNK * TOKEN_IN);
            #pragma unroll
            for (int j = 0; j < CHUNK; j++) {
                int tok = base + j;
                if (tok < total)
                    cp_async16(wdst + j * TOKEN_IN + tid * 4,
                               win + (size_t)tok * TOKEN_IN + tid * 4);
            }
            if (tid < 64) {
                int j = tid >> 3, sl = (tid & 7) * 4;
                int tok = base + j;
                if (tok < total)
                    cp_async16(idx_s + b * (CHUNK * KNB) + j * KNB + sl,
                               idx + (size_t)tok * KNB + sl);
            }
        }
        asm volatile("cp.async.commit_group;");
    };

    // prologue: chunks 0 and 1
    issue_group(bid, 0);
    issue_group(bid + grid, 1);

    int it = 0;
    for (int g = bid; g < ngroups; g += grid, ++it) {
        asm volatile("cp.async.wait_group 1;");
        __syncthreads();                      // chunk g fully visible

        const int buf  = it & 1;
        const int base = g * CHUNK;
        const float* wbuf = win_s + buf * (CHUNK * TOKEN_IN);
        const int*   ibuf = idx_s + buf * (CHUNK * KNB);
        u64* mslot = mean2 + warp * 32;

        #pragma unroll
        for (int j = 0; j < CHUNK; j++) {
            const int tok = base + j;
            if (tok >= total) break;

            // class membership (warp-uniform class c)
            const int my = ibuf[j * KNB + lane];
            unsigned mask = __ballot_sync(0xffffffffu, my == c);
            const int cnt = __popc(mask);
            const float rc = __fdividef(1.0f, (float)(cnt > 0 ? cnt : 1));

            // class-sum pair for d = 2*lane, 2*lane+1
            float s0 = 0.0f, s1 = 0.0f;
            const float2* row = (const float2*)(wbuf + j * TOKEN_IN);
            unsigned m = mask;
            while (m) {
                int k = __ffs(m) - 1;
                m &= m - 1;
                float2 v = row[k * 32 + lane];
                s0 += v.x; s1 += v.y;
            }
            __syncwarp();                     // prior GEMV reads of mslot done
            mslot[lane] = pack_f2(s0, s1);
            __syncwarp();                     // all pairs staged

            // GEMV: dot(sums, W[c][o]) * rc, then tanh
            u64 acc0 = 0ULL, acc1 = 0ULL;
            #pragma unroll
            for (int jj = 0; jj < 32; jj += 2) {
                acc0 = ffma2(mslot[jj],     w[jj],     acc0);
                acc1 = ffma2(mslot[jj + 1], w[jj + 1], acc1);
            }
            float x0, y0, x1, y1;
            unpack_f2(acc0, x0, y0);
            unpack_f2(acc1, x1, y1);
            float z = ((x0 + x1) + (y0 + y1)) * rc;

            // fast tanh: 1 - 2/(e^{2z}+1)   (abs err ~1e-7, saturates correctly)
            float e = __expf(2.0f * z);
            float y = 1.0f - __fdividef(2.0f, e + 1.0f);

            out[(size_t)tok * TOKEN_OUT + (c << 6) + o] = y;
        }

        __syncthreads();                      // all warps done reading buf
        issue_group(g + 2 * grid, buf);       // refill (guarded; always commits)
    }
}

extern "C" void kernel_launch(void* const* d_in, const int* in_sizes, int n_in,
                              void* d_out, int out_size) {
    const int*   idx = (const int*)d_in[0];   // [B,N,K] int32
    const float* win = (const float*)d_in[1]; // [B,N,K,D_IN] f32
    const float* W   = (const float*)d_in[2]; // [C,D_OUT,D_IN] f32
    float* out = (float*)d_out;               // [B,N,C,D_OUT] f32

    const int total   = in_sizes[0] / KNB;    // B*N tokens
    const int ngroups = (total + CHUNK - 1) / CHUNK;

    static int smem_set = 0;
    if (!smem_set) {
        cudaFuncSetAttribute(ordered_gcn_kernel,
                             cudaFuncAttributeMaxDynamicSharedMemorySize,
                             SMEM_BYTES);
        smem_set = 1;
    }

    int sms = 148, dev = 0;
    cudaGetDevice(&dev);
    cudaDeviceGetAttribute(&sms, cudaDevAttrMultiProcessorCount, dev);
    int grid = (sms < ngroups) ? sms : ngroups;

    ordered_gcn_kernel<<<grid, NTHR, SMEM_BYTES>>>(idx, win, W, out, total, ngroups);
}